// round 3
// baseline (speedup 1.0000x reference)
#include <cuda_runtime.h>
#include <math.h>

#define NOBJ 256
#define CCLS 151
#define DH   512
#define NC2  (CCLS * DH)   // 77312
#define TSTEPS 3

// ---------------- device scratch (module-load allocated, no runtime alloc) ----------------
__device__ float g_h[NOBJ * DH];          // current hidden state [n, D]
__device__ float g_weff[3][DH * DH];      // effective av-weights for w3w/w4w/w5w
__device__ float g_G[4][NOBJ * DH];       // h@weff3^T, h@weff4^T, h@weff5^T, h@w3u^T
__device__ float g_G5u[NOBJ * DH];        // (rv*h)@w5u^T
__device__ float g_rvh[NOBJ * DH];
__device__ float g_zv[NOBJ * DH];
__device__ float g_HS[DH];                // column sum of h
__device__ float g_v[3][DH];              // HS @ weff_k^T
__device__ float g_s[2];                  // s1 (colsum), s2 (rowsum) of matrix
__device__ float g_wcred[CCLS * DH];      // wc reduced over inner class dim
__device__ float g_out2[NOBJ * DH];       // relu output stage

// ---------------- tiny kernels ----------------

// s1 = sum_x matrix[x, 0] (column sum), s2 = sum_x matrix[0, x] (row sum)
__global__ void k_scalars(const float* __restrict__ matrix) {
    __shared__ float sa[256], sb[256];
    int t = threadIdx.x;
    float a = 0.f, b = 0.f;
    if (t < CCLS) { a = matrix[t * CCLS]; b = matrix[t]; }
    sa[t] = a; sb[t] = b;
    __syncthreads();
    for (int s = 128; s > 0; s >>= 1) {
        if (t < s) { sa[t] += sa[t + s]; sb[t] += sb[t + s]; }
        __syncthreads();
    }
    if (t == 0) { g_s[0] = sa[0]; g_s[1] = sb[0]; }
}

// weff_k[o,d] = s1*w[o,d] + s2*w[o,D+d]  for w in {w3w, w4w, w5w}
__global__ void k_weff(const float* __restrict__ w3w,
                       const float* __restrict__ w4w,
                       const float* __restrict__ w5w) {
    int idx = blockIdx.x * 256 + threadIdx.x;       // 3*512*512 total
    int which = idx >> 18;                           // / (512*512)
    int r = idx & (DH * DH - 1);
    int o = r >> 9;
    int d = r & (DH - 1);
    const float* w = (which == 0) ? w3w : (which == 1) ? w4w : w5w;
    g_weff[which][r] = g_s[0] * w[o * (2 * DH) + d] + g_s[1] * w[o * (2 * DH) + DH + d];
}

// wc_red[c,d] = sum_{c2} wc[c, c2*D + d]
__global__ void k_wcred(const float* __restrict__ wc) {
    int c = blockIdx.x;                 // 151 blocks
    int d = threadIdx.x;                // 512 threads
    const float* base = wc + (size_t)c * NC2 + d;
    float s = 0.f;
    #pragma unroll 4
    for (int c2 = 0; c2 < CCLS; c2++) s += base[c2 * DH];
    g_wcred[c * DH + d] = s;
}

// h init = input
__global__ void k_init(const float* __restrict__ input) {
    int i = blockIdx.x * 256 + threadIdx.x;
    g_h[i] = input[i];
}

// HS[d] = sum_n h[n,d]
__global__ void k_HS() {
    int d = blockIdx.x * 32 + threadIdx.x;   // grid 16, block 32
    float s = 0.f;
    #pragma unroll 8
    for (int n = 0; n < NOBJ; n++) s += g_h[n * DH + d];
    g_HS[d] = s;
}

// v_k[o] = dot(HS, weff_k[o,:])  — warp per output
__global__ void k_v() {
    int bx = blockIdx.x;                 // 3*128 blocks, 128 threads
    int k = bx >> 7;
    int ob = (bx & 127) * 4;
    int w = threadIdx.x >> 5, lane = threadIdx.x & 31;
    int o = ob + w;
    const float* row = &g_weff[k][o * DH];
    float s = 0.f;
    #pragma unroll 4
    for (int d = lane; d < DH; d += 32) s += row[d] * g_HS[d];
    #pragma unroll
    for (int off = 16; off > 0; off >>= 1) s += __shfl_xor_sync(0xffffffffu, s, off);
    if (lane == 0) g_v[k][o] = s;
}

__device__ __forceinline__ float sigmoidf(float x) { return 1.f / (1.f + expf(-x)); }

// zv, rv, rv*h
__global__ void k_gate1(const float* __restrict__ b3w, const float* __restrict__ b3u,
                        const float* __restrict__ b4w) {
    int idx = blockIdx.x * 256 + threadIdx.x;     // 131072
    int o = idx & (DH - 1);
    float G3u = g_G[3][idx];
    float bu = b3u[o];
    float z = sigmoidf(g_v[0][o] - g_G[0][idx] + b3w[o] + G3u + bu);
    float r = sigmoidf(g_v[1][o] - g_G[1][idx] + b4w[o] + G3u + bu);
    g_zv[idx] = z;
    g_rvh[idx] = r * g_h[idx];
}

// hv, h update
__global__ void k_gate2(const float* __restrict__ b5w, const float* __restrict__ b5u) {
    int idx = blockIdx.x * 256 + threadIdx.x;
    int o = idx & (DH - 1);
    float hv = tanhf(g_v[2][o] - g_G[2][idx] + b5w[o] + g_G5u[idx] + b5u[o]);
    float z = g_zv[idx];
    g_h[idx] = (1.f - z) * g_h[idx] + z * hv;
}

// ---------------- tiled SGEMM: C[M=256, N] = A[256,512] @ W[N,512]^T (+ optional 2nd pass) ----
__device__ __forceinline__ void gemm_body(
    const float* __restrict__ A, int lda,
    const float* __restrict__ W, int ldw,
    const float* __restrict__ A2, const float* __restrict__ W2,
    float* __restrict__ C, int ldc, int N,
    const float* __restrict__ bias, int act)
{
    __shared__ __align__(16) float As[16][64];
    __shared__ __align__(16) float Ws[16][64];
    int tid = threadIdx.x;
    int tx = tid & 15, ty = tid >> 4;
    int n0 = blockIdx.x * 64, m0 = blockIdx.y * 64;
    int lr = tid >> 2, lc = (tid & 3) << 2;
    float acc[4][4] = {};

    int npasses = A2 ? 2 : 1;
    for (int p = 0; p < npasses; p++) {
        const float* Ap = p ? A2 : A;
        const float* Wp = p ? W2 : W;
        for (int k0 = 0; k0 < DH; k0 += 16) {
            float4 av = *(const float4*)(Ap + (m0 + lr) * lda + k0 + lc);
            As[lc + 0][lr] = av.x; As[lc + 1][lr] = av.y;
            As[lc + 2][lr] = av.z; As[lc + 3][lr] = av.w;
            float4 wv = make_float4(0.f, 0.f, 0.f, 0.f);
            int wr = n0 + lr;
            if (wr < N) wv = *(const float4*)(Wp + wr * ldw + k0 + lc);
            Ws[lc + 0][lr] = wv.x; Ws[lc + 1][lr] = wv.y;
            Ws[lc + 2][lr] = wv.z; Ws[lc + 3][lr] = wv.w;
            __syncthreads();
            #pragma unroll
            for (int k = 0; k < 16; k++) {
                float4 a = *(const float4*)&As[k][ty << 2];
                float4 b = *(const float4*)&Ws[k][tx << 2];
                acc[0][0] += a.x * b.x; acc[0][1] += a.x * b.y;
                acc[0][2] += a.x * b.z; acc[0][3] += a.x * b.w;
                acc[1][0] += a.y * b.x; acc[1][1] += a.y * b.y;
                acc[1][2] += a.y * b.z; acc[1][3] += a.y * b.w;
                acc[2][0] += a.z * b.x; acc[2][1] += a.z * b.y;
                acc[2][2] += a.z * b.z; acc[2][3] += a.z * b.w;
                acc[3][0] += a.w * b.x; acc[3][1] += a.w * b.y;
                acc[3][2] += a.w * b.z; acc[3][3] += a.w * b.w;
            }
            __syncthreads();
        }
    }
    #pragma unroll
    for (int i = 0; i < 4; i++) {
        int m = m0 + (ty << 2) + i;
        #pragma unroll
        for (int j = 0; j < 4; j++) {
            int n = n0 + (tx << 2) + j;
            if (n < N) {
                float v = acc[i][j];
                if (bias) v += bias[n];
                if (act) v = fmaxf(v, 0.f);
                C[m * ldc + n] = v;
            }
        }
    }
}

// mode 0: z-batched {h@weff0, h@weff1, h@weff2, h@w3u} -> g_G[z]
// mode 1: rvh @ w5u^T -> g_G5u
// mode 2: relu(h@wo[:, :D]^T + input@wo[:, D:]^T + bo) -> g_out2
// mode 3: out2 @ wcred^T + bc -> final output [256, 151]
__global__ void k_gemm(int mode, const float* __restrict__ wex,
                       const float* __restrict__ aux,
                       const float* __restrict__ bex,
                       float* __restrict__ outx)
{
    const float *A, *W, *A2 = nullptr, *W2 = nullptr, *bias = nullptr;
    float* C;
    int ldw = DH, ldc = DH, N = DH, act = 0;
    if (mode == 0) {
        int z = blockIdx.z;
        A = g_h;
        W = (z == 0) ? g_weff[0] : (z == 1) ? g_weff[1] : (z == 2) ? g_weff[2] : wex;
        C = g_G[z];
    } else if (mode == 1) {
        A = g_rvh; W = wex; C = g_G5u;
    } else if (mode == 2) {
        A = g_h; W = wex; ldw = 2 * DH; A2 = aux; W2 = wex + DH;
        C = g_out2; bias = bex; act = 1;
    } else {
        A = g_out2; W = g_wcred; C = outx; N = CCLS; ldc = CCLS; bias = bex;
    }
    gemm_body(A, DH, W, ldw, A2, W2, C, ldc, N, bias, act);
}

// ---------------- host launcher ----------------
extern "C" void kernel_launch(void* const* d_in, const int* in_sizes, int n_in,
                              void* d_out, int out_size) {
    (void)in_sizes; (void)n_in; (void)out_size;
    const float* input  = (const float*)d_in[0];
    const float* matrix = (const float*)d_in[1];
    const float* w3w = (const float*)d_in[2];
    const float* b3w = (const float*)d_in[3];
    const float* w3u = (const float*)d_in[4];
    const float* b3u = (const float*)d_in[5];
    const float* w4w = (const float*)d_in[6];
    const float* b4w = (const float*)d_in[7];
    // d_in[8] = w4u, d_in[9] = b4u : unused (faithful to reference bug)
    const float* w5w = (const float*)d_in[10];
    const float* b5w = (const float*)d_in[11];
    const float* w5u = (const float*)d_in[12];
    const float* b5u = (const float*)d_in[13];
    const float* wo  = (const float*)d_in[14];
    const float* bo  = (const float*)d_in[15];
    const float* wc  = (const float*)d_in[16];
    const float* bc  = (const float*)d_in[17];
    float* out = (float*)d_out;

    k_scalars<<<1, 256>>>(matrix);
    k_weff<<<3 * DH * DH / 256, 256>>>(w3w, w4w, w5w);
    k_wcred<<<CCLS, DH>>>(wc);
    k_init<<<NOBJ * DH / 256, 256>>>(input);

    for (int t = 0; t < TSTEPS; t++) {
        k_HS<<<16, 32>>>();
        k_v<<<3 * 128, 128>>>();
        k_gemm<<<dim3(8, 4, 4), 256>>>(0, w3u, nullptr, nullptr, nullptr);
        k_gate1<<<NOBJ * DH / 256, 256>>>(b3w, b3u, b4w);
        k_gemm<<<dim3(8, 4, 1), 256>>>(1, w5u, nullptr, nullptr, nullptr);
        k_gate2<<<NOBJ * DH / 256, 256>>>(b5w, b5u);
    }

    k_gemm<<<dim3(8, 4, 1), 256>>>(2, wo, input, bo, nullptr);
    k_gemm<<<dim3(3, 4, 1), 256>>>(3, nullptr, nullptr, bc, out);
}

// round 5
// speedup vs baseline: 1.5308x; 1.5308x over previous
#include <cuda_runtime.h>
#include <math.h>

#define NOBJ 256
#define CCLS 151
#define DH   512
#define GW   2048          // G width: [weff3 | weff4(w4w) | weff5(w5w) | w3u]
#define TSTEPS 3

// ---------------- device scratch ----------------
__device__ float g_h[NOBJ * DH];
__device__ float g_weff[3][DH * DH];
__device__ float g_G[NOBJ * GW];
__device__ float g_vpart[4][GW];        // per-m-tile column sums of G
__device__ float g_zv[NOBJ * DH];
__device__ float g_rvh[NOBJ * DH];
__device__ float g_part[4][NOBJ * DH];  // K-split partials
__device__ float g_out2[NOBJ * DH];
__device__ float g_wcred[CCLS * DH];
__device__ float g_pc[8][NOBJ * 160];   // classifier K-split partials (ldc=160)
__device__ unsigned g_bar;

__global__ void k_reset() { g_bar = 0u; }

// ---------------- f32x2 helpers ----------------
__device__ __forceinline__ unsigned long long f2pack(float lo, float hi) {
    unsigned long long r;
    asm("mov.b64 %0, {%1, %2};" : "=l"(r) : "r"(__float_as_uint(lo)), "r"(__float_as_uint(hi)));
    return r;
}
__device__ __forceinline__ void ffma2(unsigned long long& d, unsigned long long a, unsigned long long b) {
    asm("fma.rn.f32x2 %0, %1, %2, %0;" : "+l"(d) : "l"(a), "l"(b));
}
__device__ __forceinline__ float2 f2unpack(unsigned long long v) {
    unsigned lo, hi;
    asm("mov.b64 {%0, %1}, %2;" : "=r"(lo), "=r"(hi) : "l"(v));
    return make_float2(__uint_as_float(lo), __uint_as_float(hi));
}

__device__ __forceinline__ float sigmoidf_(float x) { return 1.f / (1.f + __expf(-x)); }
__device__ __forceinline__ float tanhf_(float x) { return 1.f - 2.f / (__expf(2.f * x) + 1.f); }

// ---------------- global barrier ----------------
__device__ __forceinline__ void gsync(unsigned& epoch, int nb) {
    __syncthreads();
    if (threadIdx.x == 0) {
        __threadfence();
        atomicAdd(&g_bar, 1u);
        epoch += (unsigned)nb;
        while (*(volatile unsigned*)&g_bar < epoch) { __nanosleep(128); }
        __threadfence();
    }
    __syncthreads();
}

// ---------------- 64x64 tile GEMM: C = A[64,kLen] @ W[nValid,kLen]^T ----------------
// A points at A[m0][k_off]; W points at W[n0][k_off]; C points at C[m0][n0].
// If vout != null, also writes the 64 column sums of the tile to vout[0..63].
__device__ __forceinline__ void gemm_tile(
    const float* __restrict__ A, int lda,
    const float* __restrict__ W, int ldw,
    int kLen, int nValid,
    float* __restrict__ C, int ldc,
    float* __restrict__ vout,
    float (*As)[64], float (*Ws)[64])
{
    int tid = threadIdx.x;
    int tx = tid & 15, ty = tid >> 4;
    int lr = tid >> 2, lc = (tid & 3) << 2;

    unsigned long long d[2][4];
    #pragma unroll
    for (int i = 0; i < 2; i++)
        #pragma unroll
        for (int j = 0; j < 4; j++) d[i][j] = 0ull;

    for (int k0 = 0; k0 < kLen; k0 += 16) {
        float4 av = *(const float4*)(A + lr * lda + k0 + lc);
        As[lc + 0][lr] = av.x; As[lc + 1][lr] = av.y;
        As[lc + 2][lr] = av.z; As[lc + 3][lr] = av.w;
        float4 wv = make_float4(0.f, 0.f, 0.f, 0.f);
        if (lr < nValid) wv = *(const float4*)(W + lr * ldw + k0 + lc);
        Ws[lc + 0][lr] = wv.x; Ws[lc + 1][lr] = wv.y;
        Ws[lc + 2][lr] = wv.z; Ws[lc + 3][lr] = wv.w;
        __syncthreads();
        #pragma unroll
        for (int k = 0; k < 16; k++) {
            float4 a = *(const float4*)&As[k][ty << 2];
            float4 b = *(const float4*)&Ws[k][tx << 2];
            unsigned long long aP0 = f2pack(a.x, a.y), aP1 = f2pack(a.z, a.w);
            unsigned long long bP0 = f2pack(b.x, b.y), bP1 = f2pack(b.z, b.w);
            unsigned long long bS0 = f2pack(b.y, b.x), bS1 = f2pack(b.w, b.z);
            ffma2(d[0][0], aP0, bP0); ffma2(d[0][1], aP0, bS0);
            ffma2(d[0][2], aP0, bP1); ffma2(d[0][3], aP0, bS1);
            ffma2(d[1][0], aP1, bP0); ffma2(d[1][1], aP1, bS0);
            ffma2(d[1][2], aP1, bP1); ffma2(d[1][3], aP1, bS1);
        }
        __syncthreads();
    }

    // unpack: d[i2][0]=(r0c0,r1c1) d[i2][1]=(r0c1,r1c0) d[i2][2]=(r0c2,r1c3) d[i2][3]=(r0c3,r1c2)
    float acc[4][4];
    #pragma unroll
    for (int i2 = 0; i2 < 2; i2++) {
        float2 u0 = f2unpack(d[i2][0]);
        float2 u1 = f2unpack(d[i2][1]);
        float2 u2 = f2unpack(d[i2][2]);
        float2 u3 = f2unpack(d[i2][3]);
        acc[2*i2+0][0] = u0.x; acc[2*i2+1][1] = u0.y;
        acc[2*i2+0][1] = u1.x; acc[2*i2+1][0] = u1.y;
        acc[2*i2+0][2] = u2.x; acc[2*i2+1][3] = u2.y;
        acc[2*i2+0][3] = u3.x; acc[2*i2+1][2] = u3.y;
    }

    #pragma unroll
    for (int i = 0; i < 4; i++) {
        float* crow = C + (ty * 4 + i) * ldc;
        #pragma unroll
        for (int j = 0; j < 4; j++) {
            int n = (tx << 2) + j;
            if (n < nValid) crow[n] = acc[i][j];
        }
    }

    if (vout) {
        #pragma unroll
        for (int j = 0; j < 4; j++) {
            float s = acc[0][j] + acc[1][j] + acc[2][j] + acc[3][j];
            As[ty][(tx << 2) + j] = s;
        }
        __syncthreads();
        if (tid < 64) {
            float s = 0.f;
            #pragma unroll
            for (int r = 0; r < 16; r++) s += As[r][tid];
            vout[tid] = s;
        }
        __syncthreads();
    }
}

// ---------------- persistent kernel ----------------
__global__ void __launch_bounds__(256, 1) ggnn_persistent(
    const float* __restrict__ input, const float* __restrict__ matrix,
    const float* __restrict__ w3w, const float* __restrict__ b3w,
    const float* __restrict__ w3u, const float* __restrict__ b3u,
    const float* __restrict__ w4w, const float* __restrict__ b4w,
    const float* __restrict__ w5w, const float* __restrict__ b5w,
    const float* __restrict__ w5u, const float* __restrict__ b5u,
    const float* __restrict__ wo,  const float* __restrict__ bo,
    const float* __restrict__ wc,  const float* __restrict__ bc,
    float* __restrict__ out)
{
    __shared__ float As[16][64];
    __shared__ float Ws[16][64];
    __shared__ float s_red[16];
    __shared__ float s_s1, s_s2;

    const int NB = gridDim.x;
    const int bid = blockIdx.x;
    const int tid = threadIdx.x;
    const int gstride = NB * 256;
    unsigned epoch = 0;

    // ---- block-local s1 (colsum of matrix col 0), s2 (rowsum of matrix row 0) ----
    {
        float a = (tid < CCLS) ? matrix[tid * CCLS] : 0.f;
        float b = (tid < CCLS) ? matrix[tid] : 0.f;
        #pragma unroll
        for (int off = 16; off; off >>= 1) {
            a += __shfl_xor_sync(0xffffffffu, a, off);
            b += __shfl_xor_sync(0xffffffffu, b, off);
        }
        if ((tid & 31) == 0) { s_red[tid >> 5] = a; s_red[8 + (tid >> 5)] = b; }
        __syncthreads();
        if (tid == 0) {
            float sa = 0.f, sb = 0.f;
            #pragma unroll
            for (int w = 0; w < 8; w++) { sa += s_red[w]; sb += s_red[8 + w]; }
            s_s1 = sa; s_s2 = sb;
        }
        __syncthreads();
    }
    const float s1 = s_s1, s2 = s_s2;

    // ---- setup phase ----
    // weff_k[o,d] = s1*w[o,d] + s2*w[o,D+d]
    for (int u = bid * 256 + tid; u < 3 * DH * DH / 4; u += gstride) {
        int which = u >> 16;
        int r = u & 65535;
        int o = r >> 7;
        int d4 = (r & 127) << 2;
        const float* w = (which == 0) ? w3w : (which == 1) ? w4w : w5w;
        float4 lo = *(const float4*)(w + o * 2 * DH + d4);
        float4 hi = *(const float4*)(w + o * 2 * DH + DH + d4);
        float4 e;
        e.x = s1 * lo.x + s2 * hi.x; e.y = s1 * lo.y + s2 * hi.y;
        e.z = s1 * lo.z + s2 * hi.z; e.w = s1 * lo.w + s2 * hi.w;
        *(float4*)&g_weff[which][o * DH + d4] = e;
    }
    // h init
    for (int u = bid * 256 + tid; u < NOBJ * DH / 4; u += gstride)
        ((float4*)g_h)[u] = ((const float4*)input)[u];
    // wcred[c,d] = sum_c2 wc[c, c2*D + d]
    for (int c = bid; c < CCLS; c += NB) {
        const float* base = wc + (size_t)c * (CCLS * DH);
        for (int d = tid; d < DH; d += 256) {
            float s = 0.f;
            #pragma unroll 4
            for (int c2 = 0; c2 < CCLS; c2++) s += base[c2 * DH + d];
            g_wcred[c * DH + d] = s;
        }
    }
    gsync(epoch, NB);

    // ---- T steps ----
    for (int t = 0; t < TSTEPS; t++) {
        // GEMM1: G = h @ [weff0|weff1|weff2|w3u]^T  (256 x 2048), + column-sum partials
        for (int tile = bid; tile < 128; tile += NB) {
            int mt = tile & 3, nt = tile >> 2;
            int m0 = mt * 64, n0 = nt * 64;
            int z = n0 >> 9;
            const float* Wp = (z < 3) ? &g_weff[z][(n0 & 511) * DH]
                                      : (w3u + (n0 & 511) * DH);
            gemm_tile(g_h + m0 * DH, DH, Wp, DH, DH, 64,
                      g_G + m0 * GW + n0, GW, &g_vpart[mt][n0], As, Ws);
        }
        gsync(epoch, NB);

        // gate1: zv, rvh
        for (int i = bid * 256 + tid; i < NOBJ * DH; i += gstride) {
            int o = i & (DH - 1);
            float v0 = g_vpart[0][o] + g_vpart[1][o] + g_vpart[2][o] + g_vpart[3][o];
            float v1 = g_vpart[0][512 + o] + g_vpart[1][512 + o] + g_vpart[2][512 + o] + g_vpart[3][512 + o];
            const float* Grow = g_G + (i >> 9) * GW;
            float G0 = Grow[o], G1 = Grow[512 + o], G3 = Grow[1536 + o];
            float bu = b3u[o] + G3;
            float z = sigmoidf_(v0 - G0 + b3w[o] + bu);
            float r = sigmoidf_(v1 - G1 + b4w[o] + bu);
            g_zv[i] = z;
            g_rvh[i] = r * g_h[i];
        }
        gsync(epoch, NB);

        // GEMM2: g5u = rvh @ w5u^T, K-split x4
        for (int tile = bid; tile < 128; tile += NB) {
            int kc = tile & 3, mt = (tile >> 2) & 3, nt = tile >> 4;
            int m0 = mt * 64, n0 = nt * 64, k0 = kc * 128;
            gemm_tile(g_rvh + m0 * DH + k0, DH, w5u + n0 * DH + k0, DH, 128, 64,
                      g_part[kc] + m0 * DH + n0, DH, nullptr, As, Ws);
        }
        gsync(epoch, NB);

        // gate2: h update
        for (int i = bid * 256 + tid; i < NOBJ * DH; i += gstride) {
            int o = i & (DH - 1);
            float v2 = g_vpart[0][1024 + o] + g_vpart[1][1024 + o] + g_vpart[2][1024 + o] + g_vpart[3][1024 + o];
            float G2 = g_G[(i >> 9) * GW + 1024 + o];
            float g5 = g_part[0][i] + g_part[1][i] + g_part[2][i] + g_part[3][i];
            float hv = tanhf_(v2 - G2 + b5w[o] + g5 + b5u[o]);
            float z = g_zv[i];
            g_h[i] = (1.f - z) * g_h[i] + z * hv;
        }
        gsync(epoch, NB);
    }

    // GEMM3: pre-out = h@wo[:,:512]^T + input@wo[:,512:]^T, K-split over 1024
    for (int tile = bid; tile < 128; tile += NB) {
        int kc = tile & 3, mt = (tile >> 2) & 3, nt = tile >> 4;
        int m0 = mt * 64, n0 = nt * 64;
        const float* Ap; const float* Wp;
        if (kc < 2) { Ap = g_h + m0 * DH + kc * 256;   Wp = wo + n0 * (2 * DH) + kc * 256; }
        else        { Ap = input + m0 * DH + (kc - 2) * 256; Wp = wo + n0 * (2 * DH) + 512 + (kc - 2) * 256; }
        gemm_tile(Ap, DH, Wp, 2 * DH, 256, 64,
                  g_part[kc] + m0 * DH + n0, DH, nullptr, As, Ws);
    }
    gsync(epoch, NB);

    // out2 = relu(sum partials + bo)
    for (int i = bid * 256 + tid; i < NOBJ * DH; i += gstride) {
        int o = i & (DH - 1);
        float s = g_part[0][i] + g_part[1][i] + g_part[2][i] + g_part[3][i] + bo[o];
        g_out2[i] = fmaxf(s, 0.f);
    }
    gsync(epoch, NB);

    // GEMM4: out2 @ wcred^T (256 x 151), K-split x8
    for (int tile = bid; tile < 96; tile += NB) {
        int nt = tile % 3; int mt = (tile / 3) & 3; int kc = tile / 12;
        int m0 = mt * 64, n0 = nt * 64, k0 = kc * 64;
        int nv = CCLS - n0; if (nv > 64) nv = 64;
        gemm_tile(g_out2 + m0 * DH + k0, DH, g_wcred + n0 * DH + k0, DH, 64, nv,
                  g_pc[kc] + m0 * 160 + n0, 160, nullptr, As, Ws);
    }
    gsync(epoch, NB);

    // final: out = sum partials + bc
    for (int i = bid * 256 + tid; i < NOBJ * CCLS; i += gstride) {
        int n = i / CCLS, c = i - n * CCLS;
        float s = bc[c];
        #pragma unroll
        for (int kc = 0; kc < 8; kc++) s += g_pc[kc][n * 160 + c];
        out[i] = s;
    }
}

// ---------------- host launcher ----------------
extern "C" void kernel_launch(void* const* d_in, const int* in_sizes, int n_in,
                              void* d_out, int out_size) {
    (void)in_sizes; (void)n_in; (void)out_size;
    const float* input  = (const float*)d_in[0];
    const float* matrix = (const float*)d_in[1];
    const float* w3w = (const float*)d_in[2];
    const float* b3w = (const float*)d_in[3];
    const float* w3u = (const float*)d_in[4];
    const float* b3u = (const float*)d_in[5];
    const float* w4w = (const float*)d_in[6];
    const float* b4w = (const float*)d_in[7];
    // d_in[8] = w4u, d_in[9] = b4u : unused (faithful to reference bug)
    const float* w5w = (const float*)d_in[10];
    const float* b5w = (const float*)d_in[11];
    const float* w5u = (const float*)d_in[12];
    const float* b5u = (const float*)d_in[13];
    const float* wo  = (const float*)d_in[14];
    const float* bo  = (const float*)d_in[15];
    const float* wc  = (const float*)d_in[16];
    const float* bc  = (const float*)d_in[17];
    float* out = (float*)d_out;

    // Residency-proven block count: never launch more blocks than can be
    // simultaneously resident, or the software barrier would deadlock.
    int sms = 0;
    cudaDeviceGetAttribute(&sms, cudaDevAttrMultiProcessorCount, 0);
    if (sms <= 0) sms = 1;
    int perSM = 0;
    cudaOccupancyMaxActiveBlocksPerMultiprocessor(&perSM, ggnn_persistent, 256, 0);
    if (perSM <= 0) perSM = 1;
    long long cap = (long long)sms * (long long)perSM;
    int NB = (cap < 148) ? (int)cap : 148;
    if (NB < 1) NB = 1;

    k_reset<<<1, 1>>>();
    ggnn_persistent<<<NB, 256>>>(input, matrix, w3w, b3w, w3u, b3u, w4w, b4w,
                                 w5w, b5w, w5u, b5u, wo, bo, wc, bc, out);
}